// round 12
// baseline (speedup 1.0000x reference)
#include <cuda_runtime.h>
#include <cuda_bf16.h>
#include <math.h>
#include <stdint.h>

// Problem constants
#define NPOS   3
#define BSZ    2048
#define DN     128
#define NN     8192
#define XROWS  (NPOS*BSZ)
#define LOG2E10  14.426950408889634f   // 10 / ln(2)

#define TILE_BYTES 16384               // 128 rows x 128 fp8
#define PAIR_BYTES 32768               // A + B
#define SMEM_BYTES 65536               // double-buffered pairs
#define NTILE 2080                     // 64 diag + 2016 off-diag
#define NCTA  592                      // 2 CTAs/SM x 148 SMs x 2 waves

// Scratch (device globals — no allocation allowed)
__device__ uint8_t g_bA[NN * DN];      // unit rows * (10/ln2), e4m3
__device__ uint8_t g_bZ[NN * DN];      // unit rows, e4m3
__device__ float g_sumexp[NN];
__device__ float g_posp[128];
__device__ float g_lsum;
__device__ float g_posT;
__device__ int   g_done;

// ---------------------------------------------------------------- helpers
__device__ __forceinline__ uint32_t s2u(const void* p) {
    uint32_t a;
    asm("{ .reg .u64 t; cvta.to.shared.u64 t, %1; cvt.u32.u64 %0, t; }" : "=r"(a) : "l"(p));
    return a;
}
__device__ __forceinline__ float ex2(float x) {
    float y; asm("ex2.approx.ftz.f32 %0, %1;" : "=f"(y) : "f"(x)); return y;
}
__device__ __forceinline__ float lg2(float x) {
    float y; asm("lg2.approx.f32 %0, %1;" : "=f"(y) : "f"(x)); return y;
}
__device__ __forceinline__ uint16_t cvt8x2(float a, float b) {
    uint16_t r;
    asm("cvt.rn.satfinite.e4m3x2.f32 %0, %1, %2;" : "=h"(r) : "f"(a), "f"(b));
    return r;
}
__device__ __forceinline__ void ldmx4(uint32_t& r0, uint32_t& r1, uint32_t& r2,
                                      uint32_t& r3, uint32_t a) {
    asm volatile("ldmatrix.sync.aligned.m8n8.x4.shared.b16 {%0,%1,%2,%3}, [%4];"
                 : "=r"(r0), "=r"(r1), "=r"(r2), "=r"(r3) : "r"(a));
}
__device__ __forceinline__ void mmafp8(float* d, uint32_t a0, uint32_t a1,
                                       uint32_t a2, uint32_t a3,
                                       uint32_t b0, uint32_t b1) {
    asm volatile(
        "mma.sync.aligned.m16n8k32.row.col.f32.e4m3.e4m3.f32 "
        "{%0,%1,%2,%3},{%4,%5,%6,%7},{%8,%9},{%0,%1,%2,%3};"
        : "+f"(d[0]), "+f"(d[1]), "+f"(d[2]), "+f"(d[3])
        : "r"(a0), "r"(a1), "r"(a2), "r"(a3), "r"(b0), "r"(b1));
}
// first k-step: C = 0 (no accumulator zero-init needed)
__device__ __forceinline__ void mmafp8_z(float* d, uint32_t a0, uint32_t a1,
                                         uint32_t a2, uint32_t a3,
                                         uint32_t b0, uint32_t b1) {
    asm volatile(
        "mma.sync.aligned.m16n8k32.row.col.f32.e4m3.e4m3.f32 "
        "{%0,%1,%2,%3},{%4,%5,%6,%7},{%8,%9},{%10,%10,%10,%10};"
        : "=f"(d[0]), "=f"(d[1]), "=f"(d[2]), "=f"(d[3])
        : "r"(a0), "r"(a1), "r"(a2), "r"(a3), "r"(b0), "r"(b1), "f"(0.0f));
}

// decode flattened tile index -> (I, J)
__device__ __forceinline__ void decode(int g, int& I, int& J) {
    if (g < 33 * 32) { I = g / 33; J = (I + (g - I * 33)) & 63; }
    else { int h = g - 33 * 32; I = 32 + h / 32; J = (I + (h - (I - 32) * 32)) & 63; }
}

// Load one 128x128-fp8 tile into smem, XOR-swizzled (chunk c at c^(r&7)).
__device__ __forceinline__ void load_tile(uint32_t sdst, const uint8_t* src,
                                          int row0, int tid) {
#pragma unroll
    for (int i = 0; i < 4; i++) {
        int idx = i * 256 + tid;
        int r = idx >> 3;
        int c = idx & 7;
        uint32_t off = (uint32_t)r * 128u + (uint32_t)((c ^ (r & 7)) << 4);
        const char* g = (const char*)(src + (size_t)(row0 + r) * DN) + (c << 4);
        asm volatile("cp.async.cg.shared.global [%0], [%1], 16;"
                     :: "r"(sdst + off), "l"(g));
    }
}

// exp-epilogue of one ni-quarter of a finished 16-row chunk (pmi)
__device__ __forceinline__ void epi_quarter(
    const float (&a)[4][4], int pmi, int ni, bool diag,
    int wm, int wn, int tq, int tc,
    float (&rowsum)[8], float (&colsum)[8])
{
#pragma unroll
    for (int e = 0; e < 4; e++) {
        float v = ex2(a[ni][e]);
        if (diag) {
            int r  = wm + pmi * 16 + tq + (e >> 1) * 8;
            int cc = wn + ni * 8 + tc + (e & 1);
            if (r == cc) v = 0.0f;
        }
        rowsum[pmi * 2 + (e >> 1)] += v;
        if (!diag) colsum[ni * 2 + (e & 1)] += v;
    }
}

// one 16-row chunk: 16 MMAs into cur, interleaved with epilogue of prev chunk
__device__ __forceinline__ void chunk_mma(
    float (&cur)[4][4], const float (&prev)[4][4],
    bool doEpi, bool epiDiag, int pmi,
    uint32_t Abase, uint32_t arow_mi, uint32_t a7_mi,
    const uint32_t (&bf)[4][2][4], int ch,
    int wm, int wn, int tq, int tc,
    float (&rowsum)[8], float (&colsum)[8])
{
#pragma unroll
    for (int ks = 0; ks < 4; ks++) {
        uint32_t a0, a1, a2, a3;
        uint32_t c0 = (uint32_t)(ks * 2 + ch);
        ldmx4(a0, a1, a2, a3, Abase + arow_mi + ((c0 ^ a7_mi) << 4));
        if (ks == 0) {
#pragma unroll
            for (int np = 0; np < 2; np++) {
                mmafp8_z(cur[np*2],     a0, a1, a2, a3, bf[ks][np][0], bf[ks][np][2]);
                mmafp8_z(cur[np*2 + 1], a0, a1, a2, a3, bf[ks][np][1], bf[ks][np][3]);
            }
        } else {
#pragma unroll
            for (int np = 0; np < 2; np++) {
                mmafp8(cur[np*2],     a0, a1, a2, a3, bf[ks][np][0], bf[ks][np][2]);
                mmafp8(cur[np*2 + 1], a0, a1, a2, a3, bf[ks][np][1], bf[ks][np][3]);
            }
        }
        if (doEpi)
            epi_quarter(prev, pmi, ks, epiDiag, wm, wn, tq, tc, rowsum, colsum);
    }
}

// ---------------------------------------------------------------------------
// Kernel 1 (prep): blocks 0..255 normalize 4 rows/warp; blocks 256..383
// pos partials (2 b x 3 q per warp). Zeroes accumulators.
// ---------------------------------------------------------------------------
__global__ void kprep(const float* __restrict__ x, const float* __restrict__ xp)
{
    int tid  = threadIdx.x;
    int wid  = tid >> 5;
    int lane = tid & 31;
    int gid  = blockIdx.x * 256 + tid;

    if (gid < NN) g_sumexp[gid] = 0.0f;
    if (gid == 0) { g_lsum = 0.0f; g_posT = 0.0f; g_done = 0; }

    if (blockIdx.x < 256) {
        int row0 = blockIdx.x * 32 + wid * 4;
        float4 v[4];
#pragma unroll
        for (int u = 0; u < 4; u++) {
            int row = row0 + u;
            const float* src = (row < XROWS) ? (x + (size_t)row * DN)
                                             : (xp + (size_t)(row - XROWS) * DN);
            v[u] = ((const float4*)src)[lane];
        }
        float ss[4];
#pragma unroll
        for (int u = 0; u < 4; u++)
            ss[u] = v[u].x*v[u].x + v[u].y*v[u].y + v[u].z*v[u].z + v[u].w*v[u].w;
#pragma unroll
        for (int o = 16; o; o >>= 1)
#pragma unroll
            for (int u = 0; u < 4; u++)
                ss[u] += __shfl_xor_sync(0xffffffffu, ss[u], o);
#pragma unroll
        for (int u = 0; u < 4; u++) {
            float r = rsqrtf(ss[u]);
            float bx = v[u].x*r, by = v[u].y*r, bz = v[u].z*r, bw = v[u].w*r;
            ((uint32_t*)g_bZ)[(row0 + u) * 32 + lane] =
                ((uint32_t)cvt8x2(bw, bz) << 16) | cvt8x2(by, bx);
            ((uint32_t*)g_bA)[(row0 + u) * 32 + lane] =
                ((uint32_t)cvt8x2(bw*LOG2E10, bz*LOG2E10) << 16)
                | cvt8x2(by*LOG2E10, bx*LOG2E10);
        }
    } else {
        __shared__ float wsum[8];
        int pw = (blockIdx.x - 256) * 8 + wid;
        int b0 = pw * 2;
        float4 p[2];
        float4 a[2][NPOS];
#pragma unroll
        for (int i = 0; i < 2; i++)
            p[i] = ((const float4*)(xp + (size_t)(b0 + i) * DN))[lane];
#pragma unroll
        for (int i = 0; i < 2; i++)
#pragma unroll
            for (int q = 0; q < NPOS; q++)
                a[i][q] = ((const float4*)(x + (size_t)(q * BSZ + b0 + i) * DN))[lane];

        float ssp[2], ssx[2][NPOS], dt[2][NPOS];
#pragma unroll
        for (int i = 0; i < 2; i++) {
            ssp[i] = p[i].x*p[i].x + p[i].y*p[i].y + p[i].z*p[i].z + p[i].w*p[i].w;
#pragma unroll
            for (int q = 0; q < NPOS; q++) {
                float4 av = a[i][q];
                ssx[i][q] = av.x*av.x + av.y*av.y + av.z*av.z + av.w*av.w;
                dt[i][q]  = av.x*p[i].x + av.y*p[i].y + av.z*p[i].z + av.w*p[i].w;
            }
        }
#pragma unroll
        for (int o = 16; o; o >>= 1) {
#pragma unroll
            for (int i = 0; i < 2; i++) {
                ssp[i] += __shfl_xor_sync(0xffffffffu, ssp[i], o);
#pragma unroll
                for (int q = 0; q < NPOS; q++) {
                    ssx[i][q] += __shfl_xor_sync(0xffffffffu, ssx[i][q], o);
                    dt[i][q]  += __shfl_xor_sync(0xffffffffu, dt[i][q],  o);
                }
            }
        }
        float acc = 0.0f;
#pragma unroll
        for (int i = 0; i < 2; i++) {
            float rp = rsqrtf(ssp[i]);
#pragma unroll
            for (int q = 0; q < NPOS; q++)
                acc += dt[i][q] * rsqrtf(ssx[i][q]) * rp;
        }
        if (lane == 0) wsum[wid] = acc;
        __syncthreads();
        if (tid == 0) {
            float s = 0.0f;
#pragma unroll
            for (int i = 0; i < 8; i++) s += wsum[i];
            g_posp[blockIdx.x - 256] = s;
        }
    }
}

// ---------------------------------------------------------------------------
// Kernel 2: fp8 MMA with chunk-rotation pipelined exp epilogue.
// grid 592, 256 threads, 2 CTAs/SM, 64KB smem.
// ---------------------------------------------------------------------------
__global__ void __launch_bounds__(256, 2) kmain()
{
    extern __shared__ char smc[];
    uint32_t sb = s2u(smc);

    int tid  = threadIdx.x;
    int wid  = tid >> 5;
    int lane = tid & 31;

    int g0 = (blockIdx.x * NTILE) / NCTA;
    int g1 = ((blockIdx.x + 1) * NTILE) / NCTA;

    int wm = (wid & 1) * 64;
    int wn = (wid >> 1) * 32;
    int rr = lane & 15;
    int ch = lane >> 4;
    int tq = lane >> 2;
    int tc = (lane & 3) * 2;

    uint32_t arow[4]; uint32_t a7[4];
#pragma unroll
    for (int mi = 0; mi < 4; mi++) {
        int row = wm + mi * 16 + rr;
        arow[mi] = (uint32_t)row * 128u;
        a7[mi]   = (uint32_t)(row & 7);
    }
    uint32_t brow[2]; uint32_t b7[2];
#pragma unroll
    for (int np = 0; np < 2; np++) {
        int row = wn + np * 16 + rr;
        brow[np] = (uint32_t)row * 128u;
        b7[np]   = (uint32_t)(row & 7);
    }

    int I, J;
    decode(g0, I, J);
    load_tile(sb, g_bA, I * 128, tid);
    load_tile(sb + TILE_BYTES, g_bZ, J * 128, tid);
    asm volatile("cp.async.commit_group;");

    float acc0[4][4], acc1[4][4];       // 2-slot chunk rotation
    float rowsum[8], colsum[8];
#pragma unroll
    for (int i = 0; i < 8; i++) { rowsum[i] = 0.0f; colsum[i] = 0.0f; }

    bool havePrev = false, pDiag = false;
    int P_I = -1, P_J = -1;

    for (int t = g0; t < g1; t++) {
        int buf = (t - g0) & 1;
        int In = -1, Jn = -1;
        __syncthreads();                     // all warps done with buf^1
        if (t + 1 < g1) {
            decode(t + 1, In, Jn);
            uint32_t dst = sb + (uint32_t)(buf ^ 1) * PAIR_BYTES;
            load_tile(dst, g_bA, In * 128, tid);
            load_tile(dst + TILE_BYTES, g_bZ, Jn * 128, tid);
            asm volatile("cp.async.commit_group;");
            asm volatile("cp.async.wait_group 1;" ::: "memory");
        } else {
            asm volatile("cp.async.wait_group 0;" ::: "memory");
        }
        __syncthreads();

        uint32_t Abase = sb + (uint32_t)buf * PAIR_BYTES;
        uint32_t Bbase = Abase + TILE_BYTES;
        bool diag = (I == J);

        // preload all B fragments for this tile (8 ldmatrix, 32 regs)
        uint32_t bf[4][2][4];
#pragma unroll
        for (int ks = 0; ks < 4; ks++) {
            uint32_t c0 = (uint32_t)(ks * 2 + ch);
#pragma unroll
            for (int np = 0; np < 2; np++)
                ldmx4(bf[ks][np][0], bf[ks][np][1], bf[ks][np][2], bf[ks][np][3],
                      Bbase + brow[np] + ((c0 ^ b7[np]) << 4));
        }

        // chunk 0 (slot0) + epilogue of carried prev-tile chunk3 (slot1)
        chunk_mma(acc0, acc1, havePrev, pDiag, 3,
                  Abase, arow[0], a7[0], bf, ch, wm, wn, tq, tc, rowsum, colsum);

        // prev tile's sums are now complete -> flush
        if (havePrev) {
            if (!pDiag) {
#pragma unroll
                for (int i = 0; i < 8; i++) {
                    float s = colsum[i];
                    s += __shfl_xor_sync(0xffffffffu, s, 4);
                    s += __shfl_xor_sync(0xffffffffu, s, 8);
                    s += __shfl_xor_sync(0xffffffffu, s, 16);
                    colsum[i] = s;
                }
                if (lane < 4) {
#pragma unroll
                    for (int ni = 0; ni < 4; ni++)
#pragma unroll
                        for (int par = 0; par < 2; par++)
                            atomicAdd(&g_sumexp[P_J * 128 + wn + ni * 8 + lane * 2 + par],
                                      colsum[ni * 2 + par]);
                }
#pragma unroll
                for (int i = 0; i < 8; i++) colsum[i] = 0.0f;
            }
            if (P_I != I) {
                float rsv[8];
#pragma unroll
                for (int i = 0; i < 8; i++) {
                    float s = rowsum[i];
                    s += __shfl_xor_sync(0xffffffffu, s, 1);
                    s += __shfl_xor_sync(0xffffffffu, s, 2);
                    rsv[i] = s;
                    rowsum[i] = 0.0f;
                }
                if ((lane & 3) == 0) {
#pragma unroll
                    for (int mi = 0; mi < 4; mi++)
#pragma unroll
                        for (int h = 0; h < 2; h++)
                            atomicAdd(&g_sumexp[P_I * 128 + wm + mi * 16 + h * 8 + tq],
                                      rsv[mi * 2 + h]);
                }
            }
        }

        // chunks 1..3, each overlapping epilogue of the previous chunk
        chunk_mma(acc1, acc0, true, diag, 0,
                  Abase, arow[1], a7[1], bf, ch, wm, wn, tq, tc, rowsum, colsum);
        chunk_mma(acc0, acc1, true, diag, 1,
                  Abase, arow[2], a7[2], bf, ch, wm, wn, tq, tc, rowsum, colsum);
        chunk_mma(acc1, acc0, true, diag, 2,
                  Abase, arow[3], a7[3], bf, ch, wm, wn, tq, tc, rowsum, colsum);

        havePrev = true;
        pDiag = diag;
        P_I = I; P_J = J;
        I = In; J = Jn;
    }

    // drain: epilogue of the final tile's chunk3 (slot1), then flush
#pragma unroll
    for (int ni = 0; ni < 4; ni++)
        epi_quarter(acc1, 3, ni, pDiag, wm, wn, tq, tc, rowsum, colsum);

    if (!pDiag) {
#pragma unroll
        for (int i = 0; i < 8; i++) {
            float s = colsum[i];
            s += __shfl_xor_sync(0xffffffffu, s, 4);
            s += __shfl_xor_sync(0xffffffffu, s, 8);
            s += __shfl_xor_sync(0xffffffffu, s, 16);
            colsum[i] = s;
        }
        if (lane < 4) {
#pragma unroll
            for (int ni = 0; ni < 4; ni++)
#pragma unroll
                for (int par = 0; par < 2; par++)
                    atomicAdd(&g_sumexp[P_J * 128 + wn + ni * 8 + lane * 2 + par],
                              colsum[ni * 2 + par]);
        }
    }
    {
        float rsv[8];
#pragma unroll
        for (int i = 0; i < 8; i++) {
            float s = rowsum[i];
            s += __shfl_xor_sync(0xffffffffu, s, 1);
            s += __shfl_xor_sync(0xffffffffu, s, 2);
            rsv[i] = s;
        }
        if ((lane & 3) == 0) {
#pragma unroll
            for (int mi = 0; mi < 4; mi++)
#pragma unroll
                for (int h = 0; h < 2; h++)
                    atomicAdd(&g_sumexp[P_I * 128 + wm + mi * 16 + h * 8 + tq],
                              rsv[mi * 2 + h]);
        }
    }
}

// ---------------------------------------------------------------------------
// Kernel 3: log-reduce + pos combine. grid 64 x 128 threads.
// ---------------------------------------------------------------------------
__global__ void kfinal(float* __restrict__ out)
{
    __shared__ float rs[4], rp[4];
    int tid = threadIdx.x;
    int b   = blockIdx.x;

    float s = lg2(g_sumexp[b * 128 + tid]);
    float p = (tid < 2) ? g_posp[b * 2 + tid] : 0.0f;
#pragma unroll
    for (int o = 16; o; o >>= 1) {
        s += __shfl_xor_sync(0xffffffffu, s, o);
        p += __shfl_xor_sync(0xffffffffu, p, o);
    }
    if ((tid & 31) == 0) { rs[tid >> 5] = s; rp[tid >> 5] = p; }
    __syncthreads();
    if (tid == 0) {
        float sb = rs[0] + rs[1] + rs[2] + rs[3];
        float pb = rp[0] + rp[1] + rp[2] + rp[3];
        atomicAdd(&g_lsum, sb);
        atomicAdd(&g_posT, pb);
        __threadfence();
        int old = atomicAdd(&g_done, 1);
        if (old == 63) {
            const float LN2 = 0.6931471805599453f;
            float L = atomicAdd(&g_lsum, 0.0f);
            float P = atomicAdd(&g_posT, 0.0f);
            float loss_neg = L * LN2 / (float)NN + logf(4096.0f / (float)(NN - 1));
            float loss_pos = P * 10.0f / (float)XROWS;
            out[0] = loss_neg - loss_pos;
        }
    }
}

// ---------------------------------------------------------------------------
extern "C" void kernel_launch(void* const* d_in, const int* in_sizes, int n_in,
                              void* d_out, int out_size)
{
    const float* x  = (const float*)d_in[0];
    const float* xp = (const float*)d_in[1];
    if (n_in >= 2 && in_sizes[0] == BSZ * DN) {
        x  = (const float*)d_in[1];
        xp = (const float*)d_in[0];
    }

    cudaFuncSetAttribute(kmain, cudaFuncAttributeMaxDynamicSharedMemorySize, SMEM_BYTES);

    kprep<<<384, 256>>>(x, xp);
    kmain<<<NCTA, 256, SMEM_BYTES>>>();
    kfinal<<<64, 128>>>((float*)d_out);
}

// round 13
// speedup vs baseline: 1.1170x; 1.1170x over previous
#include <cuda_runtime.h>
#include <cuda_bf16.h>
#include <math.h>
#include <stdint.h>

// Problem constants
#define NPOS   3
#define BSZ    2048
#define DN     128
#define NN     8192
#define XROWS  (NPOS*BSZ)
#define LOG2E10  14.426950408889634f   // 10 / ln(2)

#define TILE_BYTES 16384               // 128 rows x 128 fp8
#define PAIR_BYTES 32768               // A + B
#define SMEM_BYTES 65536               // double-buffered pairs
#define NTILE 2080                     // 64 diag + 2016 off-diag
#define NCTA  296                      // 2 CTAs/SM x 148 SMs, single wave

// Scratch (device globals — no allocation allowed)
__device__ uint8_t g_bA[NN * DN];      // unit rows * (10/ln2), e4m3
__device__ uint8_t g_bZ[NN * DN];      // unit rows, e4m3
__device__ float g_sumexp[NN];
__device__ float g_posp[128];
__device__ float g_lsum;
__device__ float g_posT;
__device__ int   g_done;

// ---------------------------------------------------------------- helpers
__device__ __forceinline__ uint32_t s2u(const void* p) {
    uint32_t a;
    asm("{ .reg .u64 t; cvta.to.shared.u64 t, %1; cvt.u32.u64 %0, t; }" : "=r"(a) : "l"(p));
    return a;
}
__device__ __forceinline__ float ex2(float x) {
    float y; asm("ex2.approx.ftz.f32 %0, %1;" : "=f"(y) : "f"(x)); return y;
}
__device__ __forceinline__ float lg2(float x) {
    float y; asm("lg2.approx.f32 %0, %1;" : "=f"(y) : "f"(x)); return y;
}
__device__ __forceinline__ uint16_t cvt8x2(float a, float b) {
    uint16_t r;
    asm("cvt.rn.satfinite.e4m3x2.f32 %0, %1, %2;" : "=h"(r) : "f"(a), "f"(b));
    return r;
}
// accumulate via FFMA-imm form (rt_SMSP = 1 vs FADD's 2)
__device__ __forceinline__ void facc(float& s, float v) {
    s = __fmaf_rn(v, 1.0f, s);
}
__device__ __forceinline__ void ldmx4(uint32_t& r0, uint32_t& r1, uint32_t& r2,
                                      uint32_t& r3, uint32_t a) {
    asm volatile("ldmatrix.sync.aligned.m8n8.x4.shared.b16 {%0,%1,%2,%3}, [%4];"
                 : "=r"(r0), "=r"(r1), "=r"(r2), "=r"(r3) : "r"(a));
}
__device__ __forceinline__ void mmafp8(float* d, uint32_t a0, uint32_t a1,
                                       uint32_t a2, uint32_t a3,
                                       uint32_t b0, uint32_t b1) {
    asm volatile(
        "mma.sync.aligned.m16n8k32.row.col.f32.e4m3.e4m3.f32 "
        "{%0,%1,%2,%3},{%4,%5,%6,%7},{%8,%9},{%0,%1,%2,%3};"
        : "+f"(d[0]), "+f"(d[1]), "+f"(d[2]), "+f"(d[3])
        : "r"(a0), "r"(a1), "r"(a2), "r"(a3), "r"(b0), "r"(b1));
}
// first k-step: C = 0 (no accumulator zero-init needed)
__device__ __forceinline__ void mmafp8_z(float* d, uint32_t a0, uint32_t a1,
                                         uint32_t a2, uint32_t a3,
                                         uint32_t b0, uint32_t b1) {
    asm volatile(
        "mma.sync.aligned.m16n8k32.row.col.f32.e4m3.e4m3.f32 "
        "{%0,%1,%2,%3},{%4,%5,%6,%7},{%8,%9},{%10,%10,%10,%10};"
        : "=f"(d[0]), "=f"(d[1]), "=f"(d[2]), "=f"(d[3])
        : "r"(a0), "r"(a1), "r"(a2), "r"(a3), "r"(b0), "r"(b1), "f"(0.0f));
}

// decode flattened tile index -> (I, J)
__device__ __forceinline__ void decode(int g, int& I, int& J) {
    if (g < 33 * 32) { I = g / 33; J = (I + (g - I * 33)) & 63; }
    else { int h = g - 33 * 32; I = 32 + h / 32; J = (I + (h - (I - 32) * 32)) & 63; }
}

// Load one 128x128-fp8 tile into smem, XOR-swizzled (chunk c at c^(r&7)).
__device__ __forceinline__ void load_tile(uint32_t sdst, const uint8_t* src,
                                          int row0, int tid) {
#pragma unroll
    for (int i = 0; i < 4; i++) {
        int idx = i * 256 + tid;
        int r = idx >> 3;
        int c = idx & 7;
        uint32_t off = (uint32_t)r * 128u + (uint32_t)((c ^ (r & 7)) << 4);
        const char* g = (const char*)(src + (size_t)(row0 + r) * DN) + (c << 4);
        asm volatile("cp.async.cg.shared.global [%0], [%1], 16;"
                     :: "r"(sdst + off), "l"(g));
    }
}

// ---------------------------------------------------------------------------
// Kernel 1 (prep): blocks 0..255 normalize 4 rows/warp; blocks 256..383
// pos partials (2 b x 3 q per warp). Zeroes accumulators.
// ---------------------------------------------------------------------------
__global__ void kprep(const float* __restrict__ x, const float* __restrict__ xp)
{
    int tid  = threadIdx.x;
    int wid  = tid >> 5;
    int lane = tid & 31;
    int gid  = blockIdx.x * 256 + tid;

    if (gid < NN) g_sumexp[gid] = 0.0f;
    if (gid == 0) { g_lsum = 0.0f; g_posT = 0.0f; g_done = 0; }

    if (blockIdx.x < 256) {
        int row0 = blockIdx.x * 32 + wid * 4;
        float4 v[4];
#pragma unroll
        for (int u = 0; u < 4; u++) {
            int row = row0 + u;
            const float* src = (row < XROWS) ? (x + (size_t)row * DN)
                                             : (xp + (size_t)(row - XROWS) * DN);
            v[u] = ((const float4*)src)[lane];
        }
        float ss[4];
#pragma unroll
        for (int u = 0; u < 4; u++)
            ss[u] = v[u].x*v[u].x + v[u].y*v[u].y + v[u].z*v[u].z + v[u].w*v[u].w;
#pragma unroll
        for (int o = 16; o; o >>= 1)
#pragma unroll
            for (int u = 0; u < 4; u++)
                ss[u] += __shfl_xor_sync(0xffffffffu, ss[u], o);
#pragma unroll
        for (int u = 0; u < 4; u++) {
            float r = rsqrtf(ss[u]);
            float bx = v[u].x*r, by = v[u].y*r, bz = v[u].z*r, bw = v[u].w*r;
            ((uint32_t*)g_bZ)[(row0 + u) * 32 + lane] =
                ((uint32_t)cvt8x2(bw, bz) << 16) | cvt8x2(by, bx);
            ((uint32_t*)g_bA)[(row0 + u) * 32 + lane] =
                ((uint32_t)cvt8x2(bw*LOG2E10, bz*LOG2E10) << 16)
                | cvt8x2(by*LOG2E10, bx*LOG2E10);
        }
    } else {
        __shared__ float wsum[8];
        int pw = (blockIdx.x - 256) * 8 + wid;     // 0..1023
        int b0 = pw * 2;
        float4 p[2];
        float4 a[2][NPOS];
#pragma unroll
        for (int i = 0; i < 2; i++)
            p[i] = ((const float4*)(xp + (size_t)(b0 + i) * DN))[lane];
#pragma unroll
        for (int i = 0; i < 2; i++)
#pragma unroll
            for (int q = 0; q < NPOS; q++)
                a[i][q] = ((const float4*)(x + (size_t)(q * BSZ + b0 + i) * DN))[lane];

        float ssp[2], ssx[2][NPOS], dt[2][NPOS];
#pragma unroll
        for (int i = 0; i < 2; i++) {
            ssp[i] = p[i].x*p[i].x + p[i].y*p[i].y + p[i].z*p[i].z + p[i].w*p[i].w;
#pragma unroll
            for (int q = 0; q < NPOS; q++) {
                float4 av = a[i][q];
                ssx[i][q] = av.x*av.x + av.y*av.y + av.z*av.z + av.w*av.w;
                dt[i][q]  = av.x*p[i].x + av.y*p[i].y + av.z*p[i].z + av.w*p[i].w;
            }
        }
#pragma unroll
        for (int o = 16; o; o >>= 1) {
#pragma unroll
            for (int i = 0; i < 2; i++) {
                ssp[i] += __shfl_xor_sync(0xffffffffu, ssp[i], o);
#pragma unroll
                for (int q = 0; q < NPOS; q++) {
                    ssx[i][q] += __shfl_xor_sync(0xffffffffu, ssx[i][q], o);
                    dt[i][q]  += __shfl_xor_sync(0xffffffffu, dt[i][q],  o);
                }
            }
        }
        float acc = 0.0f;
#pragma unroll
        for (int i = 0; i < 2; i++) {
            float rp = rsqrtf(ssp[i]);
#pragma unroll
            for (int q = 0; q < NPOS; q++)
                acc += dt[i][q] * rsqrtf(ssx[i][q]) * rp;
        }
        if (lane == 0) wsum[wid] = acc;
        __syncthreads();
        if (tid == 0) {
            float s = 0.0f;
#pragma unroll
            for (int i = 0; i < 8; i++) s += wsum[i];
            g_posp[blockIdx.x - 256] = s;
        }
    }
}

// ---------------------------------------------------------------------------
// Kernel 2: symmetric fp8 MMA + exp, flattened balanced tiles (single wave).
// grid 296, 256 threads, 2 CTAs/SM, 64KB smem.
// ---------------------------------------------------------------------------
__global__ void __launch_bounds__(256, 2) kmain()
{
    extern __shared__ char smc[];
    uint32_t sb = s2u(smc);

    int tid  = threadIdx.x;
    int wid  = tid >> 5;
    int lane = tid & 31;

    int g0 = (blockIdx.x * NTILE) / NCTA;
    int g1 = ((blockIdx.x + 1) * NTILE) / NCTA;

    int wm = (wid & 1) * 64;
    int wn = (wid >> 1) * 32;
    int rr = lane & 15;
    int ch = lane >> 4;

    uint32_t arow[4]; uint32_t a7[4];
#pragma unroll
    for (int mi = 0; mi < 4; mi++) {
        int row = wm + mi * 16 + rr;
        arow[mi] = (uint32_t)row * 128u;
        a7[mi]   = (uint32_t)(row & 7);
    }
    uint32_t brow[2]; uint32_t b7[2];
#pragma unroll
    for (int np = 0; np < 2; np++) {
        int row = wn + np * 16 + rr;
        brow[np] = (uint32_t)row * 128u;
        b7[np]   = (uint32_t)(row & 7);
    }

    int I, J;
    decode(g0, I, J);
    load_tile(sb, g_bA, I * 128, tid);
    load_tile(sb + TILE_BYTES, g_bZ, J * 128, tid);
    asm volatile("cp.async.commit_group;");

    float rowsum[8];
#pragma unroll
    for (int i = 0; i < 8; i++) rowsum[i] = 0.0f;

    int tq = lane >> 2;
    int tc = (lane & 3) * 2;

    for (int t = g0; t < g1; t++) {
        int buf = (t - g0) & 1;
        int In = -1, Jn = -1;
        __syncthreads();                     // all warps done with buf^1
        if (t + 1 < g1) {
            decode(t + 1, In, Jn);
            uint32_t dst = sb + (uint32_t)(buf ^ 1) * PAIR_BYTES;
            load_tile(dst, g_bA, In * 128, tid);
            load_tile(dst + TILE_BYTES, g_bZ, Jn * 128, tid);
            asm volatile("cp.async.commit_group;");
            asm volatile("cp.async.wait_group 1;" ::: "memory");
        } else {
            asm volatile("cp.async.wait_group 0;" ::: "memory");
        }
        __syncthreads();

        uint32_t Abase = sb + (uint32_t)buf * PAIR_BYTES;
        uint32_t Bbase = Abase + TILE_BYTES;

        float acc[4][4][4];

#pragma unroll
        for (int ks = 0; ks < 4; ks++) {
            uint32_t c0 = (uint32_t)(ks * 2 + ch);
            uint32_t b[2][4];
#pragma unroll
            for (int np = 0; np < 2; np++)
                ldmx4(b[np][0], b[np][1], b[np][2], b[np][3],
                      Bbase + brow[np] + ((c0 ^ b7[np]) << 4));
#pragma unroll
            for (int mi = 0; mi < 4; mi++) {
                uint32_t a0, a1, a2, a3;
                ldmx4(a0, a1, a2, a3, Abase + arow[mi] + ((c0 ^ a7[mi]) << 4));
                if (ks == 0) {
#pragma unroll
                    for (int np = 0; np < 2; np++) {
                        mmafp8_z(acc[mi][np*2],     a0, a1, a2, a3, b[np][0], b[np][2]);
                        mmafp8_z(acc[mi][np*2 + 1], a0, a1, a2, a3, b[np][1], b[np][3]);
                    }
                } else {
#pragma unroll
                    for (int np = 0; np < 2; np++) {
                        mmafp8(acc[mi][np*2],     a0, a1, a2, a3, b[np][0], b[np][2]);
                        mmafp8(acc[mi][np*2 + 1], a0, a1, a2, a3, b[np][1], b[np][3]);
                    }
                }
            }
        }

        if (I == J) {
            // diagonal tile: rows only, skip r==c
#pragma unroll
            for (int mi = 0; mi < 4; mi++)
#pragma unroll
                for (int ni = 0; ni < 4; ni++)
#pragma unroll
                    for (int e = 0; e < 4; e++) {
                        int r  = wm + mi * 16 + tq + (e >> 1) * 8;
                        int cc = wn + ni * 8 + tc + (e & 1);
                        float v = ex2(acc[mi][ni][e]);
                        if (r == cc) v = 0.0f;
                        facc(rowsum[mi * 2 + (e >> 1)], v);
                    }
        } else {
            float colsum[8];
#pragma unroll
            for (int i = 0; i < 8; i++) colsum[i] = 0.0f;
#pragma unroll
            for (int mi = 0; mi < 4; mi++)
#pragma unroll
                for (int ni = 0; ni < 4; ni++)
#pragma unroll
                    for (int e = 0; e < 4; e++) {
                        float v = ex2(acc[mi][ni][e]);
                        facc(rowsum[mi * 2 + (e >> 1)], v);
                        facc(colsum[ni * 2 + (e & 1)],  v);
                    }
            // col sums -> block J rows
#pragma unroll
            for (int i = 0; i < 8; i++) {
                float s = colsum[i];
                s += __shfl_xor_sync(0xffffffffu, s, 4);
                s += __shfl_xor_sync(0xffffffffu, s, 8);
                s += __shfl_xor_sync(0xffffffffu, s, 16);
                colsum[i] = s;
            }
            if (lane < 4) {
#pragma unroll
                for (int ni = 0; ni < 4; ni++)
#pragma unroll
                    for (int par = 0; par < 2; par++)
                        atomicAdd(&g_sumexp[J * 128 + wn + ni * 8 + lane * 2 + par],
                                  colsum[ni * 2 + par]);
            }
        }

        // flush row sums when I changes (or last tile)
        if (t + 1 >= g1 || In != I) {
            float rsv[8];
#pragma unroll
            for (int i = 0; i < 8; i++) {
                float s = rowsum[i];
                s += __shfl_xor_sync(0xffffffffu, s, 1);
                s += __shfl_xor_sync(0xffffffffu, s, 2);
                rsv[i] = s;
                rowsum[i] = 0.0f;
            }
            if ((lane & 3) == 0) {
#pragma unroll
                for (int mi = 0; mi < 4; mi++)
#pragma unroll
                    for (int h = 0; h < 2; h++)
                        atomicAdd(&g_sumexp[I * 128 + wm + mi * 16 + h * 8 + tq],
                                  rsv[mi * 2 + h]);
            }
        }
        I = In; J = Jn;
    }
}

// ---------------------------------------------------------------------------
// Kernel 3: log-reduce + pos combine. grid 64 x 128 threads.
// ---------------------------------------------------------------------------
__global__ void kfinal(float* __restrict__ out)
{
    __shared__ float rs[4], rp[4];
    int tid = threadIdx.x;
    int b   = blockIdx.x;

    float s = lg2(g_sumexp[b * 128 + tid]);
    float p = (tid < 2) ? g_posp[b * 2 + tid] : 0.0f;
#pragma unroll
    for (int o = 16; o; o >>= 1) {
        s += __shfl_xor_sync(0xffffffffu, s, o);
        p += __shfl_xor_sync(0xffffffffu, p, o);
    }
    if ((tid & 31) == 0) { rs[tid >> 5] = s; rp[tid >> 5] = p; }
    __syncthreads();
    if (tid == 0) {
        float sb = rs[0] + rs[1] + rs[2] + rs[3];
        float pb = rp[0] + rp[1] + rp[2] + rp[3];
        atomicAdd(&g_lsum, sb);
        atomicAdd(&g_posT, pb);
        __threadfence();
        int old = atomicAdd(&g_done, 1);
        if (old == 63) {
            const float LN2 = 0.6931471805599453f;
            float L = atomicAdd(&g_lsum, 0.0f);
            float P = atomicAdd(&g_posT, 0.0f);
            float loss_neg = L * LN2 / (float)NN + logf(4096.0f / (float)(NN - 1));
            float loss_pos = P * 10.0f / (float)XROWS;
            out[0] = loss_neg - loss_pos;
        }
    }
}

// ---------------------------------------------------------------------------
extern "C" void kernel_launch(void* const* d_in, const int* in_sizes, int n_in,
                              void* d_out, int out_size)
{
    const float* x  = (const float*)d_in[0];
    const float* xp = (const float*)d_in[1];
    if (n_in >= 2 && in_sizes[0] == BSZ * DN) {
        x  = (const float*)d_in[1];
        xp = (const float*)d_in[0];
    }

    cudaFuncSetAttribute(kmain, cudaFuncAttributeMaxDynamicSharedMemorySize, SMEM_BYTES);

    kprep<<<384, 256>>>(x, xp);
    kmain<<<NCTA, 256, SMEM_BYTES>>>();
    kfinal<<<64, 128>>>((float*)d_out);
}